// round 15
// baseline (speedup 1.0000x reference)
#include <cuda_runtime.h>

#define NT     128   // B*T
#define BB     16
#define TT     8
#define CC     512
#define C8     64
#define HW4    196   // 784/4
#define NSLICE 16384 // rows/4

// Scratch (no device allocation -> __device__ globals; zero-initialized)
__device__ float g_xv[NT * CC];
__device__ float g_left[NT * C8];
__device__ float g_right[NT * C8];
__device__ float g_state[NT * C8];
__device__ int   g_pool_t;          // pool work ticket
__device__ int   g_scale_t;         // scale work ticket
__device__ int   g_cnt_nt[NT];      // self-resetting last-finisher counters
__device__ int   g_cnt_b[BB];
__device__ int   g_flag[BB];        // batch-ready flags

// Reset tickets/flags each launch (counters self-reset; belt & braces anyway).
__global__ void init_k() {
    int i = threadIdx.x;
    if (i == 0) { g_pool_t = 0; g_scale_t = 0; }
    if (i < BB) { g_flag[i] = 0; g_cnt_b[i] = 0; }
    if (i < NT) g_cnt_nt[i] = 0;
}

// ---------------------------------------------------------------------------
// Persistent pipelined kernel. Each block loops claiming work:
//   kind 0: pool slice (4 rows). Last nt-finisher runs that nt's gemm+BN;
//           last batch-finisher runs the scan and sets flag[b]. All wait-free.
//   kind 1: scale slice — claimed only when its batch flag is (about to be)
//           ready; x[b] is still L2-resident from pool(b) ~5us earlier.
// ---------------------------------------------------------------------------
__global__ void __launch_bounds__(256) mega_k(
    const float* __restrict__ x,
    const float* __restrict__ w1,
    const float* __restrict__ bn1g, const float* __restrict__ bn1b,
    const float* __restrict__ bn1m, const float* __restrict__ bn1v,
    const float* __restrict__ w2,
    const float* __restrict__ bn2g, const float* __restrict__ bn2b,
    const float* __restrict__ bn2m, const float* __restrict__ bn2v,
    const float* __restrict__ Wa_w, const float* __restrict__ Wa_b,
    const float* __restrict__ gamma_w, const float* __restrict__ gamma_b,
    float* __restrict__ out)
{
    __shared__ float s_part[4][2];
    __shared__ float s_sx[CC];
    __shared__ int   s_t, s_kind, s_run;

    int tid = threadIdx.x;
    int sub = tid >> 6, i = tid & 63;

    for (;;) {
        if (tid == 0) {
            int t, kind;
            int st = *(volatile int*)&g_scale_t;
            int sb = st >> 10; if (sb > BB - 1) sb = BB - 1;
            if (st < NSLICE && ((volatile int*)g_flag)[sb]) {
                t = atomicAdd(&g_scale_t, 1); kind = 1;
                if (t >= NSLICE) { t = atomicAdd(&g_pool_t, 1); kind = 0; }
            } else {
                t = atomicAdd(&g_pool_t, 1); kind = 0;
            }
            if (kind == 0 && t >= NSLICE) { t = atomicAdd(&g_scale_t, 1); kind = 1; }
            if (kind == 1 && t >= NSLICE) kind = 3;
            if (kind == 1) {                       // bounded wait (claim race only)
                int b = t >> 10;
                while (!((volatile int*)g_flag)[b]) __nanosleep(64);
                __threadfence();
            }
            s_t = t; s_kind = kind;
        }
        __syncthreads();
        int kind = s_kind, t = s_t;
        __syncthreads();                            // all read before next overwrite
        if (kind == 3) return;

        if (kind == 0) {
            // ================= POOL slice t =================
            int row = t * 4 + sub;
            const float4* xi = reinterpret_cast<const float4*>(x) + (size_t)row * HW4;
            float4 v0 = xi[i];
            float4 v1 = xi[i + 64];
            float4 v2 = xi[i + 128];
            float s = 0.f;
            if (i < 4) { float4 tv = xi[i + 192]; s = (tv.x + tv.y) + (tv.z + tv.w); }
            s += (v0.x + v0.y) + (v0.z + v0.w);
            s += (v1.x + v1.y) + (v1.z + v1.w);
            s += (v2.x + v2.y) + (v2.z + v2.w);
            #pragma unroll
            for (int o = 16; o; o >>= 1) s += __shfl_xor_sync(0xffffffffu, s, o);
            if ((i & 31) == 0) s_part[sub][i >> 5] = s;
            __syncthreads();
            if (i == 0) {
                g_xv[row] = (s_part[sub][0] + s_part[sub][1]) * (1.0f / 784.0f);
                __threadfence();                     // release this thread's xv store
            }
            __syncthreads();

            int nt = t >> 7;
            if (tid == 0) {
                int old = atomicAdd(&g_cnt_nt[nt], 1);
                if (old == 127) { g_cnt_nt[nt] = 0; s_run = nt; } else s_run = -1;
            }
            __syncthreads();
            int ntr = s_run;
            if (ntr >= 0) {
                // -------- per-nt gemm + BN + ReLU (whole block) --------
                __threadfence();
                for (int k = tid; k < CC; k += 256)
                    s_sx[k] = __ldcg(&g_xv[ntr * CC + k]);   // L2, never stale L1
                __syncthreads();
                if (tid < 128) {
                    int half = tid >> 6, ch = tid & 63;
                    const float* wsel = half ? w2   : w1;
                    const float* gsel = half ? bn2g : bn1g;
                    const float* bsel = half ? bn2b : bn1b;
                    const float* msel = half ? bn2m : bn1m;
                    const float* vsel = half ? bn2v : bn1v;
                    const float4* wr  = reinterpret_cast<const float4*>(wsel) + ch * (CC / 4);
                    const float4* sx4 = reinterpret_cast<const float4*>(s_sx);
                    float a0 = 0.f, a1 = 0.f, a2 = 0.f, a3 = 0.f;
                    #pragma unroll 8
                    for (int k = 0; k < CC / 4; k++) {
                        float4 wv = __ldg(wr + k);
                        float4 xv = sx4[k];
                        a0 += xv.x * wv.x;
                        a1 += xv.y * wv.y;
                        a2 += xv.z * wv.z;
                        a3 += xv.w * wv.w;
                    }
                    float acc = (a0 + a1) + (a2 + a3);
                    float sc  = __ldg(gsel + ch) * rsqrtf(__ldg(vsel + ch) + 1e-5f);
                    float val = fmaxf((acc - __ldg(msel + ch)) * sc + __ldg(bsel + ch), 0.f);
                    if (half == 0) g_left [ntr * C8 + ch] = val;
                    else           g_right[ntr * C8 + ch] = val;
                    __threadfence();                 // each storer releases its store
                }
                __syncthreads();
                int b = ntr >> 3;
                if (tid == 0) {
                    int old = atomicAdd(&g_cnt_b[b], 1);
                    if (old == TT - 1) { g_cnt_b[b] = 0; s_run = b; } else s_run = -1;
                }
                __syncthreads();
                int br = s_run;
                if (br >= 0 && tid < 32) {
                    // -------- per-batch scan (warp 0) --------
                    __threadfence();
                    int lane = tid;
                    float L0[7], L1[7], R0[7], R1[7];
                    #pragma unroll
                    for (int tt = 0; tt < 7; tt++) {
                        L0[tt] = __ldcg(&g_left [(br * TT + tt)     * C8 + lane]);
                        L1[tt] = __ldcg(&g_left [(br * TT + tt)     * C8 + lane + 32]);
                        R0[tt] = __ldcg(&g_right[(br * TT + tt + 1) * C8 + lane]);
                        R1[tt] = __ldcg(&g_right[(br * TT + tt + 1) * C8 + lane + 32]);
                    }
                    float gm0 = __ldg(gamma_w + lane);
                    float gm1 = __ldg(gamma_w + lane + 32);
                    float gm2 = __ldg(gamma_w + lane + 64);
                    float gm3 = __ldg(gamma_w + lane + 96);
                    float gb  = __ldg(gamma_b);
                    float s0 = 1.f, s1 = 1.f;
                    #pragma unroll
                    for (int tt = 0; tt < TT; tt++) {
                        float d0 = (tt < TT - 1) ? (L0[tt] - R0[tt]) : 1.f;
                        float d1 = (tt < TT - 1) ? (L1[tt] - R1[tt]) : 1.f;
                        float a = d0 * gm0 + d1 * gm1 + s0 * gm2 + s1 * gm3;
                        #pragma unroll
                        for (int o = 16; o; o >>= 1) a += __shfl_xor_sync(0xffffffffu, a, o);
                        float g = 1.0f / (1.0f + __expf(-(a + gb)));
                        s0 = d0 * g + s0 * (1.0f - g);
                        s1 = d1 * g + s1 * (1.0f - g);
                        g_state[(br * TT + tt) * C8 + lane]      = s0;
                        g_state[(br * TT + tt) * C8 + lane + 32] = s1;
                    }
                    __threadfence();                 // each lane releases its stores
                    __syncwarp();
                    if (lane == 0) atomicExch(&g_flag[br], 1);
                }
                __syncthreads();
            }
        } else {
            // ================= SCALE slice t (x[b] L2-resident) =================
            int row = t * 4 + sub;
            int nt  = row >> 9;
            int c   = row & (CC - 1);
            const float4* xi = reinterpret_cast<const float4*>(x)   + (size_t)row * HW4;
            float4*       xo = reinterpret_cast<float4*>(out)       + (size_t)row * HW4;

            float4 v0 = __ldg(xi + i);
            float4 v1 = __ldg(xi + i + 64);
            float4 v2 = __ldg(xi + i + 128);
            float4 v3;
            bool tail = (i < 4);
            if (tail) v3 = __ldg(xi + i + 192);

            float p = __ldcg(&g_state[nt * C8 + i]) * __ldg(Wa_w + c * C8 + i);
            #pragma unroll
            for (int o = 16; o; o >>= 1) p += __shfl_xor_sync(0xffffffffu, p, o);
            if ((i & 31) == 0) s_part[sub][i >> 5] = p;
            __syncthreads();
            float a = s_part[sub][0] + s_part[sub][1] + __ldg(Wa_b + c);
            float sg = 1.0f / (1.0f + __expf(-a));

            v0.x *= sg; v0.y *= sg; v0.z *= sg; v0.w *= sg;
            v1.x *= sg; v1.y *= sg; v1.z *= sg; v1.w *= sg;
            v2.x *= sg; v2.y *= sg; v2.z *= sg; v2.w *= sg;
            __stcs(xo + i,       v0);
            __stcs(xo + i + 64,  v1);
            __stcs(xo + i + 128, v2);
            if (tail) {
                v3.x *= sg; v3.y *= sg; v3.z *= sg; v3.w *= sg;
                __stcs(xo + i + 192, v3);
            }
            __syncthreads();
        }
    }
}

// ---------------------------------------------------------------------------
extern "C" void kernel_launch(void* const* d_in, const int* in_sizes, int n_in,
                              void* d_out, int out_size) {
    const float* x       = (const float*)d_in[0];
    const float* w1      = (const float*)d_in[1];
    const float* bn1_g   = (const float*)d_in[2];
    const float* bn1_b   = (const float*)d_in[3];
    const float* bn1_m   = (const float*)d_in[4];
    const float* bn1_v   = (const float*)d_in[5];
    const float* w2      = (const float*)d_in[6];
    const float* bn2_g   = (const float*)d_in[7];
    const float* bn2_b   = (const float*)d_in[8];
    const float* bn2_m   = (const float*)d_in[9];
    const float* bn2_v   = (const float*)d_in[10];
    const float* Wa_w    = (const float*)d_in[11];
    const float* Wa_b    = (const float*)d_in[12];
    const float* gamma_w = (const float*)d_in[13];
    const float* gamma_b = (const float*)d_in[14];
    float* out = (float*)d_out;

    init_k<<<1, 128>>>();
    mega_k<<<1184, 256>>>(x,
                          w1, bn1_g, bn1_b, bn1_m, bn1_v,
                          w2, bn2_g, bn2_b, bn2_m, bn2_v,
                          Wa_w, Wa_b, gamma_w, gamma_b, out);
}

// round 16
// speedup vs baseline: 1.1765x; 1.1765x over previous
#include <cuda_runtime.h>

#define NT   128    // B*T
#define BB   16
#define TT   8
#define CC   512
#define C8   64
#define HW4  196    // 784/4

// Scratch (no device allocation -> __device__ globals; zero-initialized)
__device__ float g_xv[NT * CC];
__device__ float g_left[NT * C8];
__device__ float g_right[NT * C8];
__device__ float g_state[NT * C8];
__device__ int   g_cnt_nt[NT];     // self-resetting last-finisher counters
__device__ int   g_cnt_b[BB];

__device__ __forceinline__ int atomic_add_release_gpu(int* addr, int v) {
    int old;
    asm volatile("atom.add.release.gpu.global.s32 %0, [%1], %2;"
                 : "=r"(old) : "l"(addr), "r"(v) : "memory");
    return old;
}
__device__ __forceinline__ void fence_acq_rel_gpu() {
    asm volatile("fence.acq_rel.gpu;" ::: "memory");
}

// ---------------------------------------------------------------------------
// Kernel 1 (merged): pool + per-nt gemm/BN/ReLU + per-batch scan.
//  - 16384 blocks pool 4 rows each (128 blocks per nt). Cross-block ordering
//    uses ONE release-atomic per block (cumulative over the block's synced
//    stores) — no MEMBAR.GPU storm (R9's failure mode).
//  - 128 winners pay fence.acq_rel + do their nt's gemm (overlapped with
//    other blocks' pooling). 16 batch-winners run the register scan.
//  - Counters self-reset -> graph-replay deterministic.
// ---------------------------------------------------------------------------
__global__ void __launch_bounds__(256) pool_gemm_scan_k(
    const float* __restrict__ x,
    const float* __restrict__ w1,
    const float* __restrict__ bn1g, const float* __restrict__ bn1b,
    const float* __restrict__ bn1m, const float* __restrict__ bn1v,
    const float* __restrict__ w2,
    const float* __restrict__ bn2g, const float* __restrict__ bn2b,
    const float* __restrict__ bn2m, const float* __restrict__ bn2v,
    const float* __restrict__ gamma_w, const float* __restrict__ gamma_b)
{
    __shared__ float s_part[4][2];
    __shared__ float s_sx[CC];
    __shared__ int   s_win;

    int tid = threadIdx.x;
    int sub = tid >> 6, i = tid & 63;
    int row = blockIdx.x * 4 + sub;          // 4 rows, all in the same nt
    const float4* xi = reinterpret_cast<const float4*>(x) + (size_t)row * HW4;

    // ---- pool (identical to proven R13 body) ----
    float4 v0 = xi[i];
    float4 v1 = xi[i + 64];
    float4 v2 = xi[i + 128];
    float s = 0.f;
    if (i < 4) { float4 tv = xi[i + 192]; s = (tv.x + tv.y) + (tv.z + tv.w); }
    s += (v0.x + v0.y) + (v0.z + v0.w);
    s += (v1.x + v1.y) + (v1.z + v1.w);
    s += (v2.x + v2.y) + (v2.z + v2.w);
    #pragma unroll
    for (int o = 16; o; o >>= 1) s += __shfl_xor_sync(0xffffffffu, s, o);
    if ((i & 31) == 0) s_part[sub][i >> 5] = s;
    __syncthreads();
    if (i == 0)
        g_xv[row] = (s_part[sub][0] + s_part[sub][1]) * (1.0f / 784.0f);
    __syncthreads();                          // block's xv stores now CTA-visible

    // ---- per-nt last-finisher election (release atomic, no fence) ----
    int nt = blockIdx.x >> 7;                 // 128 blocks per nt
    if (tid == 0) {
        int old = atomic_add_release_gpu(&g_cnt_nt[nt], 1);
        if (old == 127) { g_cnt_nt[nt] = 0; s_win = 1; } else s_win = 0;
    }
    __syncthreads();
    if (!s_win) return;

    // ---- winner: gemm + BN + ReLU for this nt ----
    fence_acq_rel_gpu();                      // acquire all 128 blocks' xv stores
    for (int k = tid; k < CC; k += 256)
        s_sx[k] = __ldcg(&g_xv[nt * CC + k]);
    __syncthreads();

    if (tid < 128) {
        int half = tid >> 6, ch = tid & 63;
        const float* wsel = half ? w2   : w1;
        const float* gsel = half ? bn2g : bn1g;
        const float* bsel = half ? bn2b : bn1b;
        const float* msel = half ? bn2m : bn1m;
        const float* vsel = half ? bn2v : bn1v;
        const float4* wr  = reinterpret_cast<const float4*>(wsel) + ch * (CC / 4);
        const float4* sx4 = reinterpret_cast<const float4*>(s_sx);
        float a0 = 0.f, a1 = 0.f, a2 = 0.f, a3 = 0.f;
        #pragma unroll 8
        for (int k = 0; k < CC / 4; k++) {
            float4 wv = __ldg(wr + k);
            float4 xv = sx4[k];
            a0 += xv.x * wv.x;
            a1 += xv.y * wv.y;
            a2 += xv.z * wv.z;
            a3 += xv.w * wv.w;
        }
        float acc = (a0 + a1) + (a2 + a3);
        float sc  = __ldg(gsel + ch) * rsqrtf(__ldg(vsel + ch) + 1e-5f);
        float val = fmaxf((acc - __ldg(msel + ch)) * sc + __ldg(bsel + ch), 0.f);
        if (half == 0) g_left [nt * C8 + ch] = val;
        else           g_right[nt * C8 + ch] = val;
    }
    __syncthreads();                          // gemm stores CTA-visible

    // ---- per-batch last-finisher election ----
    int b = nt >> 3;
    if (tid == 0) {
        int old = atomic_add_release_gpu(&g_cnt_b[b], 1);
        if (old == TT - 1) { g_cnt_b[b] = 0; s_win = 1; } else s_win = 0;
    }
    __syncthreads();
    if (!s_win || tid >= 32) return;

    // ---- batch winner: register-resident scan (warp 0) ----
    fence_acq_rel_gpu();                      // acquire all 8 nts' left/right
    int lane = tid;
    float L0[7], L1[7], R0[7], R1[7];
    #pragma unroll
    for (int t = 0; t < 7; t++) {
        L0[t] = __ldcg(&g_left [(b * TT + t)     * C8 + lane]);
        L1[t] = __ldcg(&g_left [(b * TT + t)     * C8 + lane + 32]);
        R0[t] = __ldcg(&g_right[(b * TT + t + 1) * C8 + lane]);
        R1[t] = __ldcg(&g_right[(b * TT + t + 1) * C8 + lane + 32]);
    }
    float gm0 = __ldg(gamma_w + lane);
    float gm1 = __ldg(gamma_w + lane + 32);
    float gm2 = __ldg(gamma_w + lane + 64);
    float gm3 = __ldg(gamma_w + lane + 96);
    float gb  = __ldg(gamma_b);

    float s0 = 1.f, s1 = 1.f;
    #pragma unroll
    for (int t = 0; t < TT; t++) {
        float d0 = (t < TT - 1) ? (L0[t] - R0[t]) : 1.f;
        float d1 = (t < TT - 1) ? (L1[t] - R1[t]) : 1.f;
        float a = d0 * gm0 + d1 * gm1 + s0 * gm2 + s1 * gm3;
        #pragma unroll
        for (int o = 16; o; o >>= 1) a += __shfl_xor_sync(0xffffffffu, a, o);
        float g = 1.0f / (1.0f + __expf(-(a + gb)));
        s0 = d0 * g + s0 * (1.0f - g);
        s1 = d1 * g + s1 * (1.0f - g);
        g_state[(b * TT + t) * C8 + lane]      = s0;
        g_state[(b * TT + t) * C8 + lane + 32] = s1;
    }
    // g_state consumed by the next kernel; kernel boundary provides ordering.
}

// ---------------------------------------------------------------------------
// Kernel 2: fused attention + scale. REVERSED block order (L2 reuse of the
// x tail pool left resident) + __stcs streaming stores (proven best combo).
// ---------------------------------------------------------------------------
__global__ void scale_att_k(const float* __restrict__ x,
                            const float* __restrict__ Wa_w,
                            const float* __restrict__ Wa_b,
                            float* __restrict__ out) {
    __shared__ float s_part[4][2];
    int tid  = threadIdx.x;
    int sub  = tid >> 6, i = tid & 63;
    int rb   = gridDim.x - 1 - blockIdx.x;   // reversed
    int row  = rb * 4 + sub;                 // (nt*CC + c) row id
    int nt   = row >> 9;
    int c    = row & (CC - 1);

    const float4* xi = reinterpret_cast<const float4*>(x)   + (size_t)row * HW4;
    float4*       xo = reinterpret_cast<float4*>(out)       + (size_t)row * HW4;

    float4 v0 = __ldg(xi + i);
    float4 v1 = __ldg(xi + i + 64);
    float4 v2 = __ldg(xi + i + 128);
    float4 v3;
    bool tail = (i < 4);
    if (tail) v3 = __ldg(xi + i + 192);

    float p = g_state[nt * C8 + i] * __ldg(Wa_w + c * C8 + i);
    #pragma unroll
    for (int o = 16; o; o >>= 1) p += __shfl_xor_sync(0xffffffffu, p, o);
    if ((i & 31) == 0) s_part[sub][i >> 5] = p;
    __syncthreads();
    float a = s_part[sub][0] + s_part[sub][1] + __ldg(Wa_b + c);
    float s = 1.0f / (1.0f + __expf(-a));

    v0.x *= s; v0.y *= s; v0.z *= s; v0.w *= s;
    v1.x *= s; v1.y *= s; v1.z *= s; v1.w *= s;
    v2.x *= s; v2.y *= s; v2.z *= s; v2.w *= s;
    __stcs(xo + i,       v0);
    __stcs(xo + i + 64,  v1);
    __stcs(xo + i + 128, v2);
    if (tail) {
        v3.x *= s; v3.y *= s; v3.z *= s; v3.w *= s;
        __stcs(xo + i + 192, v3);
    }
}

// ---------------------------------------------------------------------------
extern "C" void kernel_launch(void* const* d_in, const int* in_sizes, int n_in,
                              void* d_out, int out_size) {
    const float* x       = (const float*)d_in[0];
    const float* w1      = (const float*)d_in[1];
    const float* bn1_g   = (const float*)d_in[2];
    const float* bn1_b   = (const float*)d_in[3];
    const float* bn1_m   = (const float*)d_in[4];
    const float* bn1_v   = (const float*)d_in[5];
    const float* w2      = (const float*)d_in[6];
    const float* bn2_g   = (const float*)d_in[7];
    const float* bn2_b   = (const float*)d_in[8];
    const float* bn2_m   = (const float*)d_in[9];
    const float* bn2_v   = (const float*)d_in[10];
    const float* Wa_w    = (const float*)d_in[11];
    const float* Wa_b    = (const float*)d_in[12];
    const float* gamma_w = (const float*)d_in[13];
    const float* gamma_b = (const float*)d_in[14];
    float* out = (float*)d_out;

    pool_gemm_scan_k<<<(NT * CC) / 4, 256>>>(x,
                                             w1, bn1_g, bn1_b, bn1_m, bn1_v,
                                             w2, bn2_g, bn2_b, bn2_m, bn2_v,
                                             gamma_w, gamma_b);  // 16384 blocks
    scale_att_k<<<(NT * CC) / 4, 256>>>(x, Wa_w, Wa_b, out);     // 16384 blocks
}

// round 17
// speedup vs baseline: 1.9250x; 1.6363x over previous
#include <cuda_runtime.h>

#define NT   128    // B*T
#define BB   16
#define TT   8
#define CC   512
#define C8   64
#define HW4  196    // 784/4

// Scratch (no device allocation -> __device__ globals; zero-initialized)
__device__ float g_xv[NT * CC];
__device__ float g_left[NT * C8];
__device__ float g_right[NT * C8];
__device__ float g_state[NT * C8];
__device__ int   g_cnt_b[BB];      // self-resetting last-finisher counters

__device__ __forceinline__ void l2_prefetch(const void* p) {
    asm volatile("prefetch.global.L2 [%0];" :: "l"(p));
}

// ---------------------------------------------------------------------------
// Kernel 1: spatial mean pool. 4 rows/block, 64 threads/row, float4 I/O.
// Ascending block order: at completion, L2 holds the TAIL of x.
// Blocks 0..1023 also prefetch one 128B line of w1/w2 into L2 so the next
// kernel's weight loads are L2 hits (fire-and-forget, zero dependencies).
// ---------------------------------------------------------------------------
__global__ void pool_k(const float* __restrict__ x,
                       const float* __restrict__ w1,
                       const float* __restrict__ w2) {
    __shared__ float s_part[4][2];
    int tid = threadIdx.x;
    int sub = tid >> 6, i = tid & 63;
    int row = blockIdx.x * 4 + sub;
    const float4* xi = reinterpret_cast<const float4*>(x) + (size_t)row * HW4;

    if (tid == 0 && blockIdx.x < 1024) {      // warm w1/w2 (64 KB each)
        int line = blockIdx.x;
        const float* wp = (line < 512) ? (w1 + line * 32) : (w2 + (line - 512) * 32);
        l2_prefetch(wp);
    }

    float4 v0 = xi[i];
    float4 v1 = xi[i + 64];
    float4 v2 = xi[i + 128];
    float s = 0.f;
    if (i < 4) { float4 tv = xi[i + 192]; s = (tv.x + tv.y) + (tv.z + tv.w); }
    s += (v0.x + v0.y) + (v0.z + v0.w);
    s += (v1.x + v1.y) + (v1.z + v1.w);
    s += (v2.x + v2.y) + (v2.z + v2.w);

    #pragma unroll
    for (int o = 16; o; o >>= 1) s += __shfl_xor_sync(0xffffffffu, s, o);
    if ((i & 31) == 0) s_part[sub][i >> 5] = s;
    __syncthreads();
    if (i == 0)
        g_xv[row] = (s_part[sub][0] + s_part[sub][1]) * (1.0f / 784.0f);
}

// ---------------------------------------------------------------------------
// Kernel 2 (merged): gemm+BN+ReLU (128 blocks, one nt each — proven body)
// + per-batch last-finisher scan (only 128 fences/atomics grid-wide).
// Each block also prefetches 8 lines of Wa_w for the scale kernel's wave 1.
// ---------------------------------------------------------------------------
__global__ void gemm_scan_k(const float* __restrict__ w1,
                            const float* __restrict__ bn1g, const float* __restrict__ bn1b,
                            const float* __restrict__ bn1m, const float* __restrict__ bn1v,
                            const float* __restrict__ w2,
                            const float* __restrict__ bn2g, const float* __restrict__ bn2b,
                            const float* __restrict__ bn2m, const float* __restrict__ bn2v,
                            const float* __restrict__ gamma_w,
                            const float* __restrict__ gamma_b,
                            const float* __restrict__ Wa_w) {
    __shared__ float sx[CC];
    __shared__ int   s_b;
    int nt  = blockIdx.x;
    int tid = threadIdx.x;

    if (tid < 8)                               // warm Wa_w (128 KB, 1024 lines)
        l2_prefetch(Wa_w + (blockIdx.x * 8 + tid) * 32);

    #pragma unroll
    for (int i = tid; i < CC; i += 128) sx[i] = g_xv[nt * CC + i];
    __syncthreads();

    int ch = tid & 63;
    const float* wsel = (tid < 64) ? w1   : w2;
    const float* gsel = (tid < 64) ? bn1g : bn2g;
    const float* bsel = (tid < 64) ? bn1b : bn2b;
    const float* msel = (tid < 64) ? bn1m : bn2m;
    const float* vsel = (tid < 64) ? bn1v : bn2v;

    const float4* wr4 = reinterpret_cast<const float4*>(wsel + ch * CC);
    const float4* sx4 = reinterpret_cast<const float4*>(sx);
    float a0 = 0.f, a1 = 0.f, a2 = 0.f, a3 = 0.f;
    #pragma unroll 8
    for (int k = 0; k < CC / 4; k++) {
        float4 wv = __ldg(wr4 + k);
        float4 xv = sx4[k];
        a0 += xv.x * wv.x;
        a1 += xv.y * wv.y;
        a2 += xv.z * wv.z;
        a3 += xv.w * wv.w;
    }
    float acc   = (a0 + a1) + (a2 + a3);
    float scale = gsel[ch] * rsqrtf(vsel[ch] + 1e-5f);
    float val   = fmaxf((acc - msel[ch]) * scale + bsel[ch], 0.f);
    if (tid < 64) g_left[nt * C8 + ch]  = val;
    else          g_right[nt * C8 + ch] = val;

    // ---- per-batch last-finisher: run the scan ----
    __threadfence();                        // release left/right (128 blocks only)
    __syncthreads();
    int b = nt >> 3;
    if (tid == 0) {
        int old = atomicAdd(&g_cnt_b[b], 1);
        if (old == TT - 1) { g_cnt_b[b] = 0; s_b = b; } else s_b = -1;
    }
    __syncthreads();
    if (s_b < 0 || tid >= 32) return;

    __threadfence();                        // acquire left/right
    int bb = s_b, lane = tid;
    float L0[7], L1[7], R0[7], R1[7];
    #pragma unroll
    for (int t = 0; t < 7; t++) {
        L0[t] = g_left [(bb * TT + t)     * C8 + lane];
        L1[t] = g_left [(bb * TT + t)     * C8 + lane + 32];
        R0[t] = g_right[(bb * TT + t + 1) * C8 + lane];
        R1[t] = g_right[(bb * TT + t + 1) * C8 + lane + 32];
    }
    float gm0 = __ldg(gamma_w + lane);
    float gm1 = __ldg(gamma_w + lane + 32);
    float gm2 = __ldg(gamma_w + lane + 64);
    float gm3 = __ldg(gamma_w + lane + 96);
    float gb  = __ldg(gamma_b);

    float s0 = 1.f, s1 = 1.f;
    #pragma unroll
    for (int t = 0; t < TT; t++) {
        float d0 = (t < TT - 1) ? (L0[t] - R0[t]) : 1.f;
        float d1 = (t < TT - 1) ? (L1[t] - R1[t]) : 1.f;
        float a = d0 * gm0 + d1 * gm1 + s0 * gm2 + s1 * gm3;
        #pragma unroll
        for (int o = 16; o; o >>= 1) a += __shfl_xor_sync(0xffffffffu, a, o);
        float g = 1.0f / (1.0f + __expf(-(a + gb)));
        s0 = d0 * g + s0 * (1.0f - g);
        s1 = d1 * g + s1 * (1.0f - g);
        g_state[(bb * TT + t) * C8 + lane]      = s0;
        g_state[(bb * TT + t) * C8 + lane + 32] = s1;
    }
}

// ---------------------------------------------------------------------------
// Kernel 3: fused attention + scale. REVERSED block order (L2 reuse of the
// x tail pool left resident) + __stcs streaming stores (proven best combo).
// ---------------------------------------------------------------------------
__global__ void scale_att_k(const float* __restrict__ x,
                            const float* __restrict__ Wa_w,
                            const float* __restrict__ Wa_b,
                            float* __restrict__ out) {
    __shared__ float s_part[4][2];
    int tid  = threadIdx.x;
    int sub  = tid >> 6, i = tid & 63;
    int rb   = gridDim.x - 1 - blockIdx.x;   // reversed
    int row  = rb * 4 + sub;                 // (nt*CC + c) row id
    int nt   = row >> 9;
    int c    = row & (CC - 1);

    const float4* xi = reinterpret_cast<const float4*>(x)   + (size_t)row * HW4;
    float4*       xo = reinterpret_cast<float4*>(out)       + (size_t)row * HW4;

    float4 v0 = __ldg(xi + i);
    float4 v1 = __ldg(xi + i + 64);
    float4 v2 = __ldg(xi + i + 128);
    float4 v3;
    bool tail = (i < 4);
    if (tail) v3 = __ldg(xi + i + 192);

    float p = g_state[nt * C8 + i] * __ldg(Wa_w + c * C8 + i);
    #pragma unroll
    for (int o = 16; o; o >>= 1) p += __shfl_xor_sync(0xffffffffu, p, o);
    if ((i & 31) == 0) s_part[sub][i >> 5] = p;
    __syncthreads();
    float a = s_part[sub][0] + s_part[sub][1] + __ldg(Wa_b + c);
    float s = 1.0f / (1.0f + __expf(-a));

    v0.x *= s; v0.y *= s; v0.z *= s; v0.w *= s;
    v1.x *= s; v1.y *= s; v1.z *= s; v1.w *= s;
    v2.x *= s; v2.y *= s; v2.z *= s; v2.w *= s;
    __stcs(xo + i,       v0);
    __stcs(xo + i + 64,  v1);
    __stcs(xo + i + 128, v2);
    if (tail) {
        v3.x *= s; v3.y *= s; v3.z *= s; v3.w *= s;
        __stcs(xo + i + 192, v3);
    }
}

// ---------------------------------------------------------------------------
extern "C" void kernel_launch(void* const* d_in, const int* in_sizes, int n_in,
                              void* d_out, int out_size) {
    const float* x       = (const float*)d_in[0];
    const float* w1      = (const float*)d_in[1];
    const float* bn1_g   = (const float*)d_in[2];
    const float* bn1_b   = (const float*)d_in[3];
    const float* bn1_m   = (const float*)d_in[4];
    const float* bn1_v   = (const float*)d_in[5];
    const float* w2      = (const float*)d_in[6];
    const float* bn2_g   = (const float*)d_in[7];
    const float* bn2_b   = (const float*)d_in[8];
    const float* bn2_m   = (const float*)d_in[9];
    const float* bn2_v   = (const float*)d_in[10];
    const float* Wa_w    = (const float*)d_in[11];
    const float* Wa_b    = (const float*)d_in[12];
    const float* gamma_w = (const float*)d_in[13];
    const float* gamma_b = (const float*)d_in[14];
    float* out = (float*)d_out;

    pool_k<<<(NT * CC) / 4, 256>>>(x, w1, w2);               // 16384 blocks
    gemm_scan_k<<<NT, 128>>>(w1, bn1_g, bn1_b, bn1_m, bn1_v,
                             w2, bn2_g, bn2_b, bn2_m, bn2_v,
                             gamma_w, gamma_b, Wa_w);        // 128 blocks
    scale_att_k<<<(NT * CC) / 4, 256>>>(x, Wa_w, Wa_b, out); // 16384 blocks
}